// round 16
// baseline (speedup 1.0000x reference)
#include <cuda_runtime.h>
#include <cstdint>

// Graph_Learn fused, packed f32x2, STATIC single-wave schedule.
// S[b,t,i,j] = exp(relu(sum_f a_f*|xi-xj|)) / rowsum
// (row sum == reference column sum by exact bitwise symmetry of tmpS).
// 444 blocks (148 SMs x 3, all co-resident -> exactly one wave). Work = 4-row
// items; block b owns the contiguous range [b*I/444,(b+1)*I/444) -> 4-5 items
// each, 92% wave efficiency (vs 58% for the 512-block 2-wave layout).
// Contiguous items are bt-contiguous -> at most one slice restage per block.

#define Vn 256
#define Fn 64
#define TR 4            // rows per item
#define NB 444          // 148 SMs * 3 resident blocks
#define PAD 68          // floats per smem row (17 * 16B, odd quad stride)

#define SMEM_AS   (Vn * PAD)          // a[64]
#define SMEM_FLOATS (SMEM_AS + Fn)
#define SMEM_BYTES  (SMEM_FLOATS * 4)

typedef unsigned long long u64;

__device__ __forceinline__ u64 f2add(u64 a, u64 b) {
    u64 d; asm("add.rn.f32x2 %0,%1,%2;" : "=l"(d) : "l"(a), "l"(b)); return d;
}
__device__ __forceinline__ u64 f2fma(u64 a, u64 b, u64 c) {
    u64 d; asm("fma.rn.f32x2 %0,%1,%2,%3;" : "=l"(d) : "l"(a), "l"(b), "l"(c)); return d;
}
__device__ __forceinline__ u64 f2abs(u64 a) {
    u64 d; asm("and.b64 %0,%1,0x7FFFFFFF7FFFFFFF;" : "=l"(d) : "l"(a)); return d;
}
__device__ __forceinline__ u64 packf2(float lo, float hi) {
    u64 d; asm("mov.b64 %0,{%1,%2};" : "=l"(d) : "f"(lo), "f"(hi)); return d;
}
__device__ __forceinline__ void unpackf2(u64 v, float& lo, float& hi) {
    asm("mov.b64 {%0,%1},%2;" : "=f"(lo), "=f"(hi) : "l"(v));
}
__device__ __forceinline__ void lds_2x64(uint32_t addr, u64& p0, u64& p1) {
    asm volatile("ld.shared.v2.u64 {%0,%1},[%2];" : "=l"(p0), "=l"(p1) : "r"(addr));
}

__global__ __launch_bounds__(256, 3)
void gl_kernel(const float* __restrict__ x, const float* __restrict__ a,
               float* __restrict__ out, int ITEMS, int nb)
{
    extern __shared__ float sm[];
    float* xs  = sm;             // [Vn][PAD]
    float* as_ = sm + SMEM_AS;   // a[64]
    __shared__ float wsum[2][TR * 8];    // double-buffered (item parity)
    __shared__ float rdn[2][TR];

    const int tid  = threadIdx.x;
    const int j    = tid;
    const int lane = tid & 31, w = tid >> 5;
    const int b    = blockIdx.x;

    // static contiguous range: 4-5 items, bt-contiguous
    const int lo = (int)(((long long)b * ITEMS) / nb);
    const int hi = (int)(((long long)(b + 1) * ITEMS) / nb);

    if (tid < Fn) as_[tid] = a[tid];

    const uint32_t xs_sh = (uint32_t)__cvta_generic_to_shared(xs);
    const uint32_t as_sh = (uint32_t)__cvta_generic_to_shared(as_);

    int cur_bt = -1;

    #pragma unroll 1
    for (int item = lo; item < hi; ++item) {
        const int bt   = item >> 6;          // 64 4-row tiles per bt
        const int tile = item & 63;
        const int i0   = tile * TR;
        const int pp   = item & 1;           // wsum/rdn buffer parity

        if (bt != cur_bt) {
            if (cur_bt >= 0) __syncthreads();     // drain readers of old slice
            const float4* xp = (const float4*)(x + (size_t)bt * Vn * Fn);
            #pragma unroll
            for (int it = 0; it < 16; ++it) {
                int k = tid + it * 256;
                float4 v = xp[k];
                int row = k >> 4;
                int fc  = (k & 15) << 2;
                *(float4*)&xs[row * PAD + fc] = v;
            }
            cur_bt = bt;
            __syncthreads();
        }

        u64 acc[TR];
        #pragma unroll
        for (int r = 0; r < TR; ++r) acc[r] = 0ull;

        // ---- main: 8 f-chunks of 8 floats (4 packed pairs per chunk) ----
        #pragma unroll 1
        for (int c = 0; c < 8; ++c) {
            const int f0 = c << 3;
            u64 nxj[4], av[4];
            {
                const uint32_t jb = xs_sh + (uint32_t)((j * PAD + f0) * 4);
                u64 t[4];
                lds_2x64(jb + 0,  t[0], t[1]);
                lds_2x64(jb + 16, t[2], t[3]);
                #pragma unroll
                for (int q = 0; q < 4; ++q) {
                    float lx, hx; unpackf2(t[q], lx, hx);
                    nxj[q] = packf2(-lx, -hx);
                }
                const uint32_t ab = as_sh + (uint32_t)(f0 * 4);
                lds_2x64(ab + 0,  av[0], av[1]);
                lds_2x64(ab + 16, av[2], av[3]);
            }
            #pragma unroll
            for (int r = 0; r < TR; ++r) {
                const uint32_t base = xs_sh + (uint32_t)(((i0 + r) * PAD + f0) * 4);
                u64 xi[4];
                lds_2x64(base + 0,  xi[0], xi[1]);   // warp-uniform broadcast
                lds_2x64(base + 16, xi[2], xi[3]);
                u64 s = acc[r];
                #pragma unroll
                for (int k = 0; k < 4; ++k) {
                    u64 d = f2abs(f2add(xi[k], nxj[k]));   // ADD2 + 2xLOP3
                    s = f2fma(d, av[k], s);                // FFMA2
                }
                acc[r] = s;
            }
        }

        // ---- tmpS = exp(relu(lo+hi)) ----
        float f[TR];
        #pragma unroll
        for (int r = 0; r < TR; ++r) {
            float lx, hx;
            unpackf2(acc[r], lx, hx);
            f[r] = __expf(fmaxf(lx + hx, 0.f));
        }

        // ---- denom: row sums (== column sums by exact symmetry) ----
        #pragma unroll
        for (int r = 0; r < TR; ++r) {
            float v = f[r];
            v += __shfl_xor_sync(0xffffffffu, v, 16);
            v += __shfl_xor_sync(0xffffffffu, v, 8);
            v += __shfl_xor_sync(0xffffffffu, v, 4);
            v += __shfl_xor_sync(0xffffffffu, v, 2);
            v += __shfl_xor_sync(0xffffffffu, v, 1);
            if (lane == 0) wsum[pp][r * 8 + w] = v;
        }
        __syncthreads();
        if (tid < TR) {
            float d = 0.f;
            #pragma unroll
            for (int q = 0; q < 8; ++q) d += wsum[pp][tid * 8 + q];
            rdn[pp][tid] = __fdividef(1.0f, d);
        }
        __syncthreads();

        // ---- normalize + coalesced store ----
        float* op = out + ((size_t)bt * Vn + i0) * Vn + j;
        #pragma unroll
        for (int r = 0; r < TR; ++r)
            op[(size_t)r * Vn] = f[r] * rdn[pp][r];
        // next item writes the other wsum/rdn buffer -> no extra barrier
    }
}

extern "C" void kernel_launch(void* const* d_in, const int* in_sizes, int n_in,
                              void* d_out, int out_size)
{
    const float* x = (const float*)d_in[0];
    const float* a = (const float*)d_in[1];
    if (n_in >= 2 && in_sizes[0] == Fn && in_sizes[1] > Fn) {
        x = (const float*)d_in[1];
        a = (const float*)d_in[0];
    }
    int bt = in_sizes[0] == Fn ? in_sizes[1] / (Vn * Fn) : in_sizes[0] / (Vn * Fn);

    const int ITEMS = bt * (Vn / TR);        // 4-row tiles (2048 for bt=32)
    int nb = NB;
    if (nb > ITEMS) nb = ITEMS;

    cudaFuncSetAttribute(gl_kernel, cudaFuncAttributeMaxDynamicSharedMemorySize,
                         SMEM_BYTES);
    gl_kernel<<<nb, 256, SMEM_BYTES>>>(x, a, (float*)d_out, ITEMS, nb);
}

// round 17
// speedup vs baseline: 1.1889x; 1.1889x over previous
#include <cuda_runtime.h>
#include <cstdint>

// Graph_Learn fused, packed f32x2, 2-columns-per-thread register tile.
// S[b,t,i,j] = exp(relu(sum_f a_f*|xi-xj|)) / rowsum
// (row sum == reference column sum by exact bitwise symmetry of tmpS).
// Block = 16 rows x 256 cols, 256 threads. Thread owns cols (j0, j0+128) and
// 8 rows (warps 0-3: rows i0..i0+7, warps 4-7: rows i0+8..i0+15). Each
// warp-uniform xi LDS wavefront now feeds 2x the math; 2 independent
// accumulator chains per row raise ILP against the FFMA2 ladder.

#define Vn 256
#define Fn 64
#define Rr 16           // rows per block
#define HR 8            // rows per thread
#define PAD 68          // floats per smem row (17 * 16B, odd quad stride)

#define SMEM_AS   (Vn * PAD)          // a[64]
#define SMEM_FLOATS (SMEM_AS + Fn)
#define SMEM_BYTES  (SMEM_FLOATS * 4)

typedef unsigned long long u64;

__device__ __forceinline__ u64 f2add(u64 a, u64 b) {
    u64 d; asm("add.rn.f32x2 %0,%1,%2;" : "=l"(d) : "l"(a), "l"(b)); return d;
}
__device__ __forceinline__ u64 f2fma(u64 a, u64 b, u64 c) {
    u64 d; asm("fma.rn.f32x2 %0,%1,%2,%3;" : "=l"(d) : "l"(a), "l"(b), "l"(c)); return d;
}
__device__ __forceinline__ u64 f2abs(u64 a) {
    u64 d; asm("and.b64 %0,%1,0x7FFFFFFF7FFFFFFF;" : "=l"(d) : "l"(a)); return d;
}
__device__ __forceinline__ u64 packf2(float lo, float hi) {
    u64 d; asm("mov.b64 %0,{%1,%2};" : "=l"(d) : "f"(lo), "f"(hi)); return d;
}
__device__ __forceinline__ void unpackf2(u64 v, float& lo, float& hi) {
    asm("mov.b64 {%0,%1},%2;" : "=f"(lo), "=f"(hi) : "l"(v));
}
__device__ __forceinline__ void lds_2x64(uint32_t addr, u64& p0, u64& p1) {
    asm volatile("ld.shared.v2.u64 {%0,%1},[%2];" : "=l"(p0), "=l"(p1) : "r"(addr));
}

__global__ __launch_bounds__(256, 3)
void gl_kernel(const float* __restrict__ x, const float* __restrict__ a,
               float* __restrict__ out)
{
    extern __shared__ float sm[];
    float* xs  = sm;             // [Vn][PAD]
    float* as_ = sm + SMEM_AS;   // a[64]
    __shared__ float wsum[Rr * 4];   // [row][4 warps-of-that-half]
    __shared__ float rdn[Rr];

    const int tid = threadIdx.x;
    const int j0  = tid & 127;           // first column
    const int h   = tid >> 7;            // row-half (0/1)
    const int bt  = blockIdx.y;
    const int i0  = blockIdx.x * Rr + h * HR;  // this thread's 8 rows

    // ---- stage x[bt] slice into padded smem (coalesced LDG.128) ----
    const float4* xp = (const float4*)(x + (size_t)bt * Vn * Fn);
    #pragma unroll
    for (int it = 0; it < 16; ++it) {
        int k = tid + it * 256;
        float4 v = xp[k];
        int row = k >> 4;
        int fc  = (k & 15) << 2;
        *(float4*)&xs[row * PAD + fc] = v;
    }
    if (tid < Fn) as_[tid] = a[tid];
    __syncthreads();

    const uint32_t xs_sh = (uint32_t)__cvta_generic_to_shared(xs);
    const uint32_t as_sh = (uint32_t)__cvta_generic_to_shared(as_);

    u64 acc0[HR], acc1[HR];
    #pragma unroll
    for (int r = 0; r < HR; ++r) { acc0[r] = 0ull; acc1[r] = 0ull; }

    // ---- main: 8 f-chunks of 8 floats (4 packed pairs per chunk) ----
    #pragma unroll 1
    for (int c = 0; c < 8; ++c) {
        const int f0 = c << 3;
        u64 nx0[4], nx1[4], av[4];
        {
            const uint32_t jb0 = xs_sh + (uint32_t)((j0 * PAD + f0) * 4);
            const uint32_t jb1 = jb0 + (uint32_t)(128 * PAD * 4);
            u64 t[4];
            lds_2x64(jb0 + 0,  t[0], t[1]);
            lds_2x64(jb0 + 16, t[2], t[3]);
            #pragma unroll
            for (int q = 0; q < 4; ++q) {
                float lx, hx; unpackf2(t[q], lx, hx);
                nx0[q] = packf2(-lx, -hx);
            }
            lds_2x64(jb1 + 0,  t[0], t[1]);
            lds_2x64(jb1 + 16, t[2], t[3]);
            #pragma unroll
            for (int q = 0; q < 4; ++q) {
                float lx, hx; unpackf2(t[q], lx, hx);
                nx1[q] = packf2(-lx, -hx);
            }
            const uint32_t ab = as_sh + (uint32_t)(f0 * 4);
            lds_2x64(ab + 0,  av[0], av[1]);
            lds_2x64(ab + 16, av[2], av[3]);
        }
        #pragma unroll
        for (int r = 0; r < HR; ++r) {
            const uint32_t base = xs_sh + (uint32_t)(((i0 + r) * PAD + f0) * 4);
            u64 xi[4];
            lds_2x64(base + 0,  xi[0], xi[1]);   // warp-uniform broadcast
            lds_2x64(base + 16, xi[2], xi[3]);
            u64 s0 = acc0[r], s1 = acc1[r];      // 2 independent chains
            #pragma unroll
            for (int k = 0; k < 4; ++k) {
                u64 d0 = f2abs(f2add(xi[k], nx0[k]));
                u64 d1 = f2abs(f2add(xi[k], nx1[k]));
                s0 = f2fma(d0, av[k], s0);
                s1 = f2fma(d1, av[k], s1);
            }
            acc0[r] = s0; acc1[r] = s1;
        }
    }

    // ---- tmpS = exp(relu(lo+hi)) ----
    float f0v[HR], f1v[HR];
    #pragma unroll
    for (int r = 0; r < HR; ++r) {
        float lx, hx;
        unpackf2(acc0[r], lx, hx);
        f0v[r] = __expf(fmaxf(lx + hx, 0.f));
        unpackf2(acc1[r], lx, hx);
        f1v[r] = __expf(fmaxf(lx + hx, 0.f));
    }

    // ---- denom: row sums (== column sums by exact symmetry) ----
    const int lane = tid & 31;
    const int wq   = (tid >> 5) & 3;     // warp index within the row-half
    #pragma unroll
    for (int r = 0; r < HR; ++r) {
        float v = f0v[r] + f1v[r];       // 64 cols per warp
        v += __shfl_xor_sync(0xffffffffu, v, 16);
        v += __shfl_xor_sync(0xffffffffu, v, 8);
        v += __shfl_xor_sync(0xffffffffu, v, 4);
        v += __shfl_xor_sync(0xffffffffu, v, 2);
        v += __shfl_xor_sync(0xffffffffu, v, 1);
        if (lane == 0) wsum[(h * HR + r) * 4 + wq] = v;
    }
    __syncthreads();
    if (tid < Rr) {
        float d = 0.f;
        #pragma unroll
        for (int q = 0; q < 4; ++q) d += wsum[tid * 4 + q];
        rdn[tid] = __fdividef(1.0f, d);
    }
    __syncthreads();

    // ---- normalize + coalesced store (two 128B segments per warp-row) ----
    float* op = out + ((size_t)bt * Vn + i0) * Vn + j0;
    #pragma unroll
    for (int r = 0; r < HR; ++r) {
        const float rc = rdn[h * HR + r];
        op[(size_t)r * Vn]       = f0v[r] * rc;
        op[(size_t)r * Vn + 128] = f1v[r] * rc;
    }
}

extern "C" void kernel_launch(void* const* d_in, const int* in_sizes, int n_in,
                              void* d_out, int out_size)
{
    const float* x = (const float*)d_in[0];
    const float* a = (const float*)d_in[1];
    if (n_in >= 2 && in_sizes[0] == Fn && in_sizes[1] > Fn) {
        x = (const float*)d_in[1];
        a = (const float*)d_in[0];
    }
    int bt = in_sizes[0] == Fn ? in_sizes[1] / (Vn * Fn) : in_sizes[0] / (Vn * Fn);

    cudaFuncSetAttribute(gl_kernel, cudaFuncAttributeMaxDynamicSharedMemorySize,
                         SMEM_BYTES);
    dim3 grid(Vn / Rr, bt);      // bt slow: co-resident blocks share the slice
    gl_kernel<<<grid, 256, SMEM_BYTES>>>(x, a, (float*)d_out);
}